// round 15
// baseline (speedup 1.0000x reference)
#include <cuda_runtime.h>
#include <math.h>
#include <stdint.h>

// ----------------------------------------------------------------------------
// ODELSTMCell: B=16384, I=128, H=256
// R11: MT=32 rows/CTA (512 CTAs), **512 threads** (16 warps/SM), tile TJ=2 x TM=8.
// R10 showed L1 off the critical path (63.5%) but issue/fma capped ~50% at
// 8 warps. Same swizzled layout; per k per SM: 64 wf vs 64 FMA-cyc (1:1),
// with 16 warps to actually cover LDS/LDG latency.
// Buffers [256 cols][32 rows] fp32, XOR swizzle on 16B chunks:
//   phys(c,m) = c*32 + 4*((m>>2) ^ (c&7)) + (m&3)
// 7 buffers x 32KB = 224 KB smem, 1 CTA/SM.
// ----------------------------------------------------------------------------

#define B_TOTAL 16384
#define HDIM    256
#define IDIM    128
#define MT      32     // batch rows per CTA  (512 CTAs)
#define NB      8192   // floats per state buffer (256*32)
#define NSTEPS  8
#define TPB     512

// swizzled float offset of logical (col c, row-chunk q) [16B chunk of 4 rows]
#define SWZ(c, q) ((c) * 32 + 4 * ((q) ^ ((c) & 7)))

// --- packed transposed weight scratch ---
__device__ float2 g_W1p [HDIM * 128];
__device__ float2 g_W2p [HDIM * 128];
__device__ float2 g_Wihp[IDIM * 512];
__device__ float2 g_Whhp[HDIM * 512];

__global__ void prep_kernel(const float* __restrict__ W1, const float* __restrict__ W2,
                            const float* __restrict__ Wih, const float* __restrict__ Whh) {
    int i0 = blockIdx.x * blockDim.x + threadIdx.x;
    int gs = gridDim.x * blockDim.x;
    for (int p = i0; p < HDIM * 128; p += gs) {           // p = k*128 + jj
        int k = p >> 7, jj = p & 127;
        g_W1p[p] = make_float2(W1[jj * HDIM + k], W1[(jj + 128) * HDIM + k]);
        g_W2p[p] = make_float2(W2[jj * HDIM + k], W2[(jj + 128) * HDIM + k]);
    }
    for (int p = i0; p < IDIM * 512; p += gs) {           // p = k*512 + q*128 + jj
        int k = p >> 9, r = p & 511, q = r >> 7, jj = r & 127;
        int j0 = q * 256 + jj;
        g_Wihp[p] = make_float2(Wih[j0 * IDIM + k], Wih[(j0 + 128) * IDIM + k]);
    }
    for (int p = i0; p < HDIM * 512; p += gs) {
        int k = p >> 9, r = p & 511, q = r >> 7, jj = r & 127;
        int j0 = q * 256 + jj;
        g_Whhp[p] = make_float2(Whh[j0 * HDIM + k], Whh[(j0 + 128) * HDIM + k]);
    }
}

// --- packed fp32x2 FMA (sm_100+): d = a*b + d ---
__device__ __forceinline__ void ffma2(float2& d, float2 a, float2 b) {
    asm("fma.rn.f32x2 %0, %1, %2, %0;"
        : "+l"(*reinterpret_cast<unsigned long long*>(&d))
        : "l"(*reinterpret_cast<const unsigned long long*>(&a)),
          "l"(*reinterpret_cast<const unsigned long long*>(&b)));
}

__device__ __forceinline__ float4 LD4(const float* p) { return *reinterpret_cast<const float4*>(p); }
__device__ __forceinline__ void  ST4(float* p, float4 v) { *reinterpret_cast<float4*>(p) = v; }
__device__ __forceinline__ float sigm(float x) { return 1.0f / (1.0f + expf(-x)); }

// GEMM core: thread computes 2 columns {jj, jj+128} x 8 rows (chunks q0, q0+1).
//   acc[0..3]: col jj      (row pairs within chunks q0, q0+1)
//   acc[4..7]: col jj+128
// inT: swizzled smem buffer base; Wc: global packed float2, row stride RW.
// Weight prefetch one 8-k chunk ahead; activation LDS.128 broadcast inline.
// Relies on k0 % 8 == 0, so (k0+i)&7 == i.
template<int K, int RW>
__device__ __forceinline__ void gemm2(const float* __restrict__ inT,
                                      int q0,
                                      const float2* __restrict__ Wc,
                                      float2 acc[8]) {
    const float2* wp = Wc;
    float2 w[8];
#pragma unroll
    for (int i = 0; i < 8; i++) w[i] = wp[i * RW];
#pragma unroll 1
    for (int k0 = 0; k0 < K; k0 += 8) {
        const float2* wnp = (k0 + 8 < K) ? (wp + 8 * RW) : Wc;  // dummy on last
        float2 wn[8];
#pragma unroll
        for (int i = 0; i < 8; i++) wn[i] = wnp[i * RW];
#pragma unroll
        for (int i = 0; i < 8; i++) {
            const float* colp = inT + (k0 + i) * 32;   // col k0+i base
            float4 a0 = LD4(colp + 4 * ((q0 + 0) ^ i));
            float4 a1 = LD4(colp + 4 * ((q0 + 1) ^ i));
            float2 wx = make_float2(w[i].x, w[i].x);
            float2 wy = make_float2(w[i].y, w[i].y);
            ffma2(acc[0], make_float2(a0.x, a0.y), wx);
            ffma2(acc[1], make_float2(a0.z, a0.w), wx);
            ffma2(acc[2], make_float2(a1.x, a1.y), wx);
            ffma2(acc[3], make_float2(a1.z, a1.w), wx);
            ffma2(acc[4], make_float2(a0.x, a0.y), wy);
            ffma2(acc[5], make_float2(a0.z, a0.w), wy);
            ffma2(acc[6], make_float2(a1.x, a1.y), wy);
            ffma2(acc[7], make_float2(a1.z, a1.w), wy);
        }
#pragma unroll
        for (int i = 0; i < 8; i++) w[i] = wn[i];
        wp += 8 * RW;
    }
}

// one evaluation of f: out = tanh(in @ W1^T + b1) @ W2^T + b2
// Tb MAY ALIAS inT: a __syncthreads separates gemm1 reads from Tb writes.
// ACCH: accumulate h += dt * (11/84) * f(in).
template<bool ACCH>
__device__ __forceinline__ void feval(const float* __restrict__ inT,
                                      float* __restrict__ outT,
                                      float* __restrict__ Tb,
                                      const float* __restrict__ DTs,
                                      int jj, int aoff,
                                      float b1a, float b1b, float b2a, float b2b) {
    const int q0 = aoff >> 2;
    float2 acc[8];
#pragma unroll
    for (int i = 0; i < 8; i++) acc[i] = make_float2(0.f, 0.f);
    gemm2<HDIM, 128>(inT, q0, g_W1p + jj, acc);
    __syncthreads();   // all gemm1 reads of inT done before Tb (possibly ==inT) writes
#pragma unroll
    for (int j = 0; j < 2; j++) {
        float4 v0 = make_float4(tanhf(acc[2*j].x + b1a),   tanhf(acc[2*j].y + b1a),
                                tanhf(acc[2*j+1].x + b1a), tanhf(acc[2*j+1].y + b1a));
        float4 v1 = make_float4(tanhf(acc[4+2*j].x + b1b),   tanhf(acc[4+2*j].y + b1b),
                                tanhf(acc[4+2*j+1].x + b1b), tanhf(acc[4+2*j+1].y + b1b));
        ST4(Tb + SWZ(jj, q0 + j), v0);
        ST4(Tb + SWZ(jj + 128, q0 + j), v1);
    }
    __syncthreads();
#pragma unroll
    for (int i = 0; i < 8; i++) acc[i] = make_float2(0.f, 0.f);
    gemm2<HDIM, 128>(Tb, q0, g_W2p + jj, acc);
#pragma unroll
    for (int j = 0; j < 2; j++) {
        float* p0 = outT + SWZ(jj, q0 + j);
        float* p1 = outT + SWZ(jj + 128, q0 + j);
        if (ACCH) {
            const float C6 = (float)(11.0 / 84.0);
            float4 dtv = LD4(DTs + aoff + 4 * j);
            float4 h0v = LD4(p0), h1v = LD4(p1);
            h0v.x += dtv.x * C6 * (acc[2*j].x + b2a);
            h0v.y += dtv.y * C6 * (acc[2*j].y + b2a);
            h0v.z += dtv.z * C6 * (acc[2*j+1].x + b2a);
            h0v.w += dtv.w * C6 * (acc[2*j+1].y + b2a);
            h1v.x += dtv.x * C6 * (acc[4+2*j].x + b2b);
            h1v.y += dtv.y * C6 * (acc[4+2*j].y + b2b);
            h1v.z += dtv.z * C6 * (acc[4+2*j+1].x + b2b);
            h1v.w += dtv.w * C6 * (acc[4+2*j+1].y + b2b);
            ST4(p0, h0v);
            ST4(p1, h1v);
        } else {
            ST4(p0, make_float4(acc[2*j].x + b2a,   acc[2*j].y + b2a,
                                acc[2*j+1].x + b2a, acc[2*j+1].y + b2a));
            ST4(p1, make_float4(acc[4+2*j].x + b2b,   acc[4+2*j].y + b2b,
                                acc[4+2*j+1].x + b2b, acc[4+2*j+1].y + b2b));
        }
    }
    __syncthreads();
}

#define SMEM_FLOATS (7 * NB + MT)
#define SMEM_BYTES  (SMEM_FLOATS * 4)   // 229504 B -> 1 CTA/SM

__global__ void __launch_bounds__(TPB, 1)
ode_lstm_kernel(const float* __restrict__ x,  const float* __restrict__ h0,
                const float* __restrict__ c0, const float* __restrict__ ts,
                const float* __restrict__ b_ih, const float* __restrict__ b_hh,
                const float* __restrict__ b1,   const float* __restrict__ b2,
                float* __restrict__ out) {
    extern __shared__ float s[];
    float* Hs = s;
    float* K1 = s + 1 * NB;
    float* K2 = s + 2 * NB;
    float* K3 = s + 3 * NB;
    float* K4 = s + 4 * NB;
    float* K5 = s + 5 * NB;
    float* AT = s + 6 * NB;           // A-stage / tanh scratch; XT overlay later
    float* DTs = s + 7 * NB;          // [MT] per-row dt

    const int t = threadIdx.x;
    const int rowBase = blockIdx.x * MT;

    // GEMM mapping: 2 columns x 8 rows per thread
    const int jj   = t & 127;
    const int aoff = (t >> 7) * 8;    // 0, 8, 16, 24

    // Flat elementwise mapping: 4 passes, physical float4 at index t + 512*i.
    // Logical row chunk is pass-invariant: qe = (t&7) ^ ((t>>3)&7)
    // (512-float4 stride: col advances by 64 -> col&7 unchanged; chunk t&7 unchanged).
    const int qe = (t & 7) ^ ((t >> 3) & 7);
    const int ft = 4 * t;

    // I/O mapping: col = t&255, half = (t>>8)*16
    const int colIO = t & 255;
    const int mIO   = (t >> 8) * 16;

    // ---- loads ----
#pragma unroll 1
    for (int mm = 0; mm < 16; mm++) {
        int m = mIO + mm;
        Hs[SWZ(colIO, m >> 2) + (m & 3)] = h0[(size_t)(rowBase + m) * HDIM + colIO];
    }
    if (t < MT) DTs[t] = ts[rowBase + t] * (1.0f / NSTEPS);
    const float b1a = b1[jj], b1b = b1[jj + 128];
    const float b2a = b2[jj], b2b = b2[jj + 128];
    __syncthreads();

    const float4 dte4 = LD4(DTs + 4 * qe);   // dt for this thread's 4 rows (flat phases)

    // dopri5 tableau
    const float A21 = 0.2f;
    const float A31 = 0.075f, A32 = 0.225f;
    const float A41 = (float)(44.0 / 45.0), A42 = (float)(-56.0 / 15.0), A43 = (float)(32.0 / 9.0);
    const float A51 = (float)(19372.0 / 6561.0), A52 = (float)(-25360.0 / 2187.0),
                A53 = (float)(64448.0 / 6561.0), A54 = (float)(-212.0 / 729.0);
    const float A61 = (float)(9017.0 / 3168.0), A62 = (float)(-355.0 / 33.0),
                A63 = (float)(46732.0 / 5247.0), A64 = (float)(49.0 / 176.0),
                A65 = (float)(-5103.0 / 18656.0);
    const float C1 = (float)(35.0 / 384.0), C3 = (float)(500.0 / 1113.0),
                C4 = (float)(125.0 / 192.0), C5 = (float)(-2187.0 / 6784.0);

    // ================= ODE: 8 RK45 steps =================
#pragma unroll 1
    for (int step = 0; step < NSTEPS; step++) {
        // k1 = f(h)
        feval<false>(Hs, K1, AT, DTs, jj, aoff, b1a, b1b, b2a, b2b);

        // A = h + dt*a21*k1
#pragma unroll
        for (int i = 0; i < 4; i++) {
            int p = ft + 2048 * i;
            float4 h = LD4(Hs + p), k1v = LD4(K1 + p), av;
            av.x = h.x + dte4.x * (A21 * k1v.x);
            av.y = h.y + dte4.y * (A21 * k1v.y);
            av.z = h.z + dte4.z * (A21 * k1v.z);
            av.w = h.w + dte4.w * (A21 * k1v.w);
            ST4(AT + p, av);
        }
        __syncthreads();
        feval<false>(AT, K2, AT, DTs, jj, aoff, b1a, b1b, b2a, b2b);

        // A = h + dt*(a31 k1 + a32 k2)
#pragma unroll
        for (int i = 0; i < 4; i++) {
            int p = ft + 2048 * i;
            float4 h = LD4(Hs + p), k1v = LD4(K1 + p), k2v = LD4(K2 + p), av;
            av.x = h.x + dte4.x * (A31 * k1v.x + A32 * k2v.x);
            av.y = h.y + dte4.y * (A31 * k1v.y + A32 * k2v.y);
            av.z = h.z + dte4.z * (A31 * k1v.z + A32 * k2v.z);
            av.w = h.w + dte4.w * (A31 * k1v.w + A32 * k2v.w);
            ST4(AT + p, av);
        }
        __syncthreads();
        feval<false>(AT, K3, AT, DTs, jj, aoff, b1a, b1b, b2a, b2b);

        // A = h + dt*(a41 k1 + a42 k2 + a43 k3)
#pragma unroll
        for (int i = 0; i < 4; i++) {
            int p = ft + 2048 * i;
            float4 h = LD4(Hs + p), k1v = LD4(K1 + p), k2v = LD4(K2 + p), k3v = LD4(K3 + p), av;
            av.x = h.x + dte4.x * (A41 * k1v.x + A42 * k2v.x + A43 * k3v.x);
            av.y = h.y + dte4.y * (A41 * k1v.y + A42 * k2v.y + A43 * k3v.y);
            av.z = h.z + dte4.z * (A41 * k1v.z + A42 * k2v.z + A43 * k3v.z);
            av.w = h.w + dte4.w * (A41 * k1v.w + A42 * k2v.w + A43 * k3v.w);
            ST4(AT + p, av);
        }
        __syncthreads();
        feval<false>(AT, K4, AT, DTs, jj, aoff, b1a, b1b, b2a, b2b);

        // A = h + dt*(a51 k1 + a52 k2 + a53 k3 + a54 k4)
#pragma unroll
        for (int i = 0; i < 4; i++) {
            int p = ft + 2048 * i;
            float4 h = LD4(Hs + p), k1v = LD4(K1 + p), k2v = LD4(K2 + p),
                   k3v = LD4(K3 + p), k4v = LD4(K4 + p), av;
            av.x = h.x + dte4.x * (A51 * k1v.x + A52 * k2v.x + A53 * k3v.x + A54 * k4v.x);
            av.y = h.y + dte4.y * (A51 * k1v.y + A52 * k2v.y + A53 * k3v.y + A54 * k4v.y);
            av.z = h.z + dte4.z * (A51 * k1v.z + A52 * k2v.z + A53 * k3v.z + A54 * k4v.z);
            av.w = h.w + dte4.w * (A51 * k1v.w + A52 * k2v.w + A53 * k3v.w + A54 * k4v.w);
            ST4(AT + p, av);
        }
        __syncthreads();
        feval<false>(AT, K5, AT, DTs, jj, aoff, b1a, b1b, b2a, b2b);

        // A = h + dt*(a61..a65 · k);  h = h + dt*(c1 k1 + c3 k3 + c4 k4 + c5 k5)
#pragma unroll
        for (int i = 0; i < 4; i++) {
            int p = ft + 2048 * i;
            float4 h = LD4(Hs + p), k1v = LD4(K1 + p), k2v = LD4(K2 + p),
                   k3v = LD4(K3 + p), k4v = LD4(K4 + p), k5v = LD4(K5 + p), av, hn;
            av.x = h.x + dte4.x * (A61 * k1v.x + A62 * k2v.x + A63 * k3v.x + A64 * k4v.x + A65 * k5v.x);
            av.y = h.y + dte4.y * (A61 * k1v.y + A62 * k2v.y + A63 * k3v.y + A64 * k4v.y + A65 * k5v.y);
            av.z = h.z + dte4.z * (A61 * k1v.z + A62 * k2v.z + A63 * k3v.z + A64 * k4v.z + A65 * k5v.z);
            av.w = h.w + dte4.w * (A61 * k1v.w + A62 * k2v.w + A63 * k3v.w + A64 * k4v.w + A65 * k5v.w);
            hn.x = h.x + dte4.x * (C1 * k1v.x + C3 * k3v.x + C4 * k4v.x + C5 * k5v.x);
            hn.y = h.y + dte4.y * (C1 * k1v.y + C3 * k3v.y + C4 * k4v.y + C5 * k5v.y);
            hn.z = h.z + dte4.z * (C1 * k1v.z + C3 * k3v.z + C4 * k4v.z + C5 * k5v.z);
            hn.w = h.w + dte4.w * (C1 * k1v.w + C3 * k3v.w + C4 * k4v.w + C5 * k5v.w);
            ST4(AT + p, av);
            ST4(Hs + p, hn);
        }
        __syncthreads();
        // k6 = f(A); h += dt*(11/84)*k6  (fused epilogue)
        feval<true>(AT, Hs, AT, DTs, jj, aoff, b1a, b1b, b2a, b2b);
    }

    // ================= two weight-shared LSTM cells =================
    float* Cs = K5;  // alias free buffers
    float* G0 = K1; float* G1 = K2; float* G2 = K3; float* G3 = K4;
    float* XT = AT;  // [128][32] swizzled overlay — AT free now

#pragma unroll 1
    for (int mm = 0; mm < 16; mm++) {
        int m = mIO + mm;
        Cs[SWZ(colIO, m >> 2) + (m & 3)] = c0[(size_t)(rowBase + m) * HDIM + colIO];
    }
    {
        int cx = t & 127, m0 = (t >> 7) * 8;
#pragma unroll 1
        for (int mm = 0; mm < 8; mm++) {
            int m = m0 + mm;
            XT[SWZ(cx, m >> 2) + (m & 3)] = x[(size_t)(rowBase + m) * IDIM + cx];
        }
    }
    __syncthreads();

    const int q0 = aoff >> 2;
#pragma unroll 1
    for (int cell = 0; cell < 2; cell++) {
#pragma unroll 1
        for (int qg = 0; qg < 4; qg++) {
            float2 acc[8];
#pragma unroll
            for (int i = 0; i < 8; i++) acc[i] = make_float2(0.f, 0.f);
            gemm2<IDIM, 512>(XT, q0, g_Wihp + qg * 128 + jj, acc);
            gemm2<HDIM, 512>(Hs, q0, g_Whhp + qg * 128 + jj, acc);
            const float bza = b_ih[qg * 256 + jj]       + b_hh[qg * 256 + jj];
            const float bzb = b_ih[qg * 256 + jj + 128] + b_hh[qg * 256 + jj + 128];
            float* Gq = (qg == 0) ? G0 : (qg == 1) ? G1 : (qg == 2) ? G2 : G3;
#pragma unroll
            for (int j = 0; j < 2; j++) {
                float va0 = acc[2*j].x + bza,   va1 = acc[2*j].y + bza;
                float va2 = acc[2*j+1].x + bza, va3 = acc[2*j+1].y + bza;
                float vb0 = acc[4+2*j].x + bzb,   vb1 = acc[4+2*j].y + bzb;
                float vb2 = acc[4+2*j+1].x + bzb, vb3 = acc[4+2*j+1].y + bzb;
                float4 o0, o1;
                if (qg == 2) {
                    o0 = make_float4(tanhf(va0), tanhf(va1), tanhf(va2), tanhf(va3));
                    o1 = make_float4(tanhf(vb0), tanhf(vb1), tanhf(vb2), tanhf(vb3));
                } else {
                    o0 = make_float4(sigm(va0), sigm(va1), sigm(va2), sigm(va3));
                    o1 = make_float4(sigm(vb0), sigm(vb1), sigm(vb2), sigm(vb3));
                }
                ST4(Gq + SWZ(jj, q0 + j), o0);
                ST4(Gq + SWZ(jj + 128, q0 + j), o1);
            }
        }
        __syncthreads();
#pragma unroll
        for (int i = 0; i < 4; i++) {
            int p = ft + 2048 * i;
            float4 iv = LD4(G0 + p), fv = LD4(G1 + p), gv = LD4(G2 + p), ov = LD4(G3 + p);
            float4 cv = LD4(Cs + p), cn, hv;
            cn.x = fv.x * cv.x + iv.x * gv.x;
            cn.y = fv.y * cv.y + iv.y * gv.y;
            cn.z = fv.z * cv.z + iv.z * gv.z;
            cn.w = fv.w * cv.w + iv.w * gv.w;
            hv.x = ov.x * tanhf(cn.x);
            hv.y = ov.y * tanhf(cn.y);
            hv.z = ov.z * tanhf(cn.z);
            hv.w = ov.w * tanhf(cn.w);
            ST4(Cs + p, cn);
            ST4(Hs + p, hv);
        }
        __syncthreads();
    }

    // ---- store h2 then c2 (coalesced across t) ----
    const size_t BH = (size_t)B_TOTAL * HDIM;
#pragma unroll 1
    for (int mm = 0; mm < 16; mm++) {
        int m = mIO + mm;
        int sp = SWZ(colIO, m >> 2) + (m & 3);
        out[(size_t)(rowBase + m) * HDIM + colIO]      = Hs[sp];
        out[BH + (size_t)(rowBase + m) * HDIM + colIO] = Cs[sp];
    }
}

extern "C" void kernel_launch(void* const* d_in, const int* in_sizes, int n_in,
                              void* d_out, int out_size) {
    const float* x    = (const float*)d_in[0];
    const float* h0   = (const float*)d_in[1];
    const float* c0   = (const float*)d_in[2];
    const float* ts   = (const float*)d_in[3];
    const float* W_ih = (const float*)d_in[4];
    const float* W_hh = (const float*)d_in[5];
    const float* b_ih = (const float*)d_in[6];
    const float* b_hh = (const float*)d_in[7];
    const float* W1   = (const float*)d_in[8];
    const float* b1   = (const float*)d_in[9];
    const float* W2   = (const float*)d_in[10];
    const float* b2   = (const float*)d_in[11];
    float* out = (float*)d_out;

    cudaFuncSetAttribute(ode_lstm_kernel,
                         cudaFuncAttributeMaxDynamicSharedMemorySize, SMEM_BYTES);

    prep_kernel<<<512, 256>>>(W1, W2, W_ih, W_hh);
    ode_lstm_kernel<<<B_TOTAL / MT, TPB, SMEM_BYTES>>>(
        x, h0, c0, ts, b_ih, b_hh, b1, b2, out);
}

// round 17
// speedup vs baseline: 1.3312x; 1.3312x over previous
#include <cuda_runtime.h>
#include <cuda_bf16.h>
#include <math.h>
#include <stdint.h>

#define BT 16384
#define NSTEPS 8

// ---- weights in mma-fragment layout (u32 = bf16 pair), hi/lo split ----
__device__ uint32_t W1fh[32768], W1fl[32768], W2fh[32768], W2fl[32768];
__device__ uint32_t Whhfh[131072], Whhfl[131072];
__device__ uint32_t Wihfh[65536],  Wihfl[65536];
// ---- state in fragment layout: [cta][mt 8][n8 32][reg 4][lane 32] ----
#define NSLOT 4194304
__device__ float gH[NSLOT], gC[NSLOT];
__device__ float gK1[NSLOT], gK2[NSLOT], gK3[NSLOT], gK4[NSLOT], gK5[NSLOT];

__constant__ float CF[5][5] = {
    {0.2f, 0.f, 0.f, 0.f, 0.f},
    {0.075f, 0.225f, 0.f, 0.f, 0.f},
    {44.f/45.f, -56.f/15.f, 32.f/9.f, 0.f, 0.f},
    {19372.f/6561.f, -25360.f/2187.f, 64448.f/6561.f, -212.f/729.f, 0.f},
    {9017.f/3168.f, -355.f/33.f, 46732.f/5247.f, 49.f/176.f, -5103.f/18656.f}};
#define C1f (35.f/384.f)
#define C3f (500.f/1113.f)
#define C4f (125.f/192.f)
#define C5f (-2187.f/6784.f)
#define C6f (11.f/84.f)

__device__ __forceinline__ void mma8(float d[4], const uint32_t a[4], const uint32_t b[2]) {
    asm volatile(
        "mma.sync.aligned.m16n8k16.row.col.f32.bf16.bf16.f32 "
        "{%0,%1,%2,%3},{%4,%5,%6,%7},{%8,%9},{%0,%1,%2,%3};"
        : "+f"(d[0]), "+f"(d[1]), "+f"(d[2]), "+f"(d[3])
        : "r"(a[0]), "r"(a[1]), "r"(a[2]), "r"(a[3]), "r"(b[0]), "r"(b[1]));
}
__device__ __forceinline__ void split2(float v0, float v1, uint32_t& hi, uint32_t& lo) {
    __nv_bfloat16 h0 = __float2bfloat16(v0), h1 = __float2bfloat16(v1);
    __nv_bfloat162 H(h0, h1);
    __nv_bfloat162 L(__float2bfloat16(v0 - __bfloat162float(h0)),
                     __float2bfloat16(v1 - __bfloat162float(h1)));
    hi = *(uint32_t*)&H;
    lo = *(uint32_t*)&L;
}
__device__ __forceinline__ float sigm(float v) { return 1.0f / (1.0f + expf(-v)); }

// ---- prep: weights -> fragment-layout hi/lo bf16 images ----
__global__ void prep_w(const float* __restrict__ W1, const float* __restrict__ W2,
                       const float* __restrict__ Wih, const float* __restrict__ Whh) {
    int i0 = blockIdx.x * blockDim.x + threadIdx.x, gs = gridDim.x * blockDim.x;
    for (int s = i0; s < 32768; s += gs) {
        int la = s & 31, hf = (s >> 5) & 1, n8 = (s >> 6) & 31, kt = s >> 11;
        int n = n8 * 8 + (la >> 2), k = kt * 16 + hf * 8 + 2 * (la & 3);
        split2(W1[n * 256 + k], W1[n * 256 + k + 1], W1fh[s], W1fl[s]);
        split2(W2[n * 256 + k], W2[n * 256 + k + 1], W2fh[s], W2fl[s]);
    }
    for (int s = i0; s < 131072; s += gs) {
        int g = s >> 15, s2 = s & 32767;
        int la = s2 & 31, hf = (s2 >> 5) & 1, n8 = (s2 >> 6) & 31, kt = s2 >> 11;
        int j = g * 256 + n8 * 8 + (la >> 2), k = kt * 16 + hf * 8 + 2 * (la & 3);
        split2(Whh[j * 256 + k], Whh[j * 256 + k + 1], Whhfh[s], Whhfl[s]);
    }
    for (int s = i0; s < 65536; s += gs) {
        int g = s >> 14, s2 = s & 16383;
        int la = s2 & 31, hf = (s2 >> 5) & 1, n8 = (s2 >> 6) & 31, kt = s2 >> 11;  // kt 0..7
        int j = g * 256 + n8 * 8 + (la >> 2), k = kt * 16 + hf * 8 + 2 * (la & 3);
        split2(Wih[j * 128 + k], Wih[j * 128 + k + 1], Wihfh[s], Wihfl[s]);
    }
}

// GEMM: acc[2][16][4] += A(frag smem, hi/lo) @ B(frag global, hi/lo)^T (bf16x3)
// A slot: ((mt*AK + kt8)*2 + half)*32 + lane ; B slot: ((kt16*32 + n8)*2 + half)*32 + lane
__device__ __forceinline__ void gemm_acc(
    const uint32_t* __restrict__ Ah, const uint32_t* __restrict__ Al, int AK,
    const uint32_t* __restrict__ Bh, const uint32_t* __restrict__ Bl,
    int KT16, int mw, int nw, int l, float acc[2][16][4])
{
#pragma unroll 1
    for (int kt = 0; kt < KT16; kt++) {
        uint32_t ah[2][4], alo[2][4];
#pragma unroll
        for (int i = 0; i < 2; i++) {
            int ab = (((2 * mw + i) * AK + 2 * kt) * 2) * 32 + l;
            ah[i][0] = Ah[ab];      ah[i][1] = Ah[ab + 32];
            ah[i][2] = Ah[ab + 64]; ah[i][3] = Ah[ab + 96];
            alo[i][0] = Al[ab];      alo[i][1] = Al[ab + 32];
            alo[i][2] = Al[ab + 64]; alo[i][3] = Al[ab + 96];
        }
#pragma unroll
        for (int nt = 0; nt < 16; nt++) {
            int bb = ((kt * 32 + nw * 16 + nt) * 2) * 32 + l;
            uint32_t bh[2] = {Bh[bb], Bh[bb + 32]};
            uint32_t bl[2] = {Bl[bb], Bl[bb + 32]};
#pragma unroll
            for (int i = 0; i < 2; i++) {
                mma8(acc[i][nt], ah[i], bh);
                mma8(acc[i][nt], ah[i], bl);
                mma8(acc[i][nt], alo[i], bh);
            }
        }
    }
}

#define ZACC()  { _Pragma("unroll") for (int i = 0; i < 2; i++) _Pragma("unroll") \
                  for (int nt = 0; nt < 16; nt++) _Pragma("unroll") \
                  for (int r = 0; r < 4; r++) acc[i][nt][r] = 0.f; }

#define SMEM_SZ (50816 * 4)

__global__ void __launch_bounds__(256, 1)
ode_main(const float* __restrict__ x, const float* __restrict__ h0,
         const float* __restrict__ c0, const float* __restrict__ ts,
         const float* __restrict__ b_ih, const float* __restrict__ b_hh,
         const float* __restrict__ b1, const float* __restrict__ b2,
         float* __restrict__ out)
{
    extern __shared__ __align__(16) uint32_t sm[];
    uint32_t* AH = sm;               // 16384 u32  (A hi frags)
    uint32_t* AL = sm + 16384;       // A lo
    uint32_t* XH = sm + 32768;       // 8192 u32   (x hi frags)
    uint32_t* XL = sm + 40960;
    float* B1S = (float*)(sm + 49152);
    float* B2S = (float*)(sm + 49408);
    float* BZS = (float*)(sm + 49664);   // 1024
    float* DTS = (float*)(sm + 50688);   // 128

    const int t = threadIdx.x, l = t & 31, w = t >> 5;
    const int mw = w >> 1, nw = w & 1;
    const int rb = blockIdx.x * 128;
    const size_t cbb = (size_t)blockIdx.x * 32768;

    B1S[t] = b1[t];
    B2S[t] = b2[t];
#pragma unroll
    for (int i = 0; i < 4; i++) BZS[i * 256 + t] = b_ih[i * 256 + t] + b_hh[i * 256 + t];
    if (t < 128) DTS[t] = ts[rb + t] * (1.0f / NSTEPS);

    // init: A = h0 frags; gH = h0; gC = c0 (fragment layout)
#pragma unroll 1
    for (int s = t; s < 16384; s += 256) {
        int la = s & 31, hf = (s >> 5) & 1, k8 = (s >> 6) & 31, mt = s >> 11;
        int r = mt * 16 + hf * 8 + (la >> 2), c = k8 * 8 + 2 * (la & 3);
        size_t gsrc = (size_t)(rb + r) * 256 + c;
        float v0 = h0[gsrc], v1 = h0[gsrc + 1];
        split2(v0, v1, AH[s], AL[s]);
        size_t gi = cbb + (size_t)(((mt * 32 + k8) * 4 + hf * 2) * 32 + la);
        gH[gi] = v0;          gH[gi + 32] = v1;
        gC[gi] = c0[gsrc];    gC[gi + 32] = c0[gsrc + 1];
    }
    __syncthreads();

    float acc[2][16][4];

    // ================= ODE: 8 steps x 6 stages =================
#pragma unroll 1
    for (int it = 0; it < NSTEPS * 6; it++) {
        int stg = (it % 6) + 1;
        // GEMM1: D = A @ W1^T
        ZACC();
        gemm_acc(AH, AL, 32, W1fh, W1fl, 16, mw, nw, l, acc);
        __syncthreads();
        // epi1: A = tanh(D + b1)
#pragma unroll
        for (int i = 0; i < 2; i++) {
            int mt = 2 * mw + i;
#pragma unroll
            for (int nt = 0; nt < 16; nt++) {
                int n8 = nw * 16 + nt, ci = n8 * 8 + 2 * (l & 3);
                float q0 = tanhf(acc[i][nt][0] + B1S[ci]);
                float q1 = tanhf(acc[i][nt][1] + B1S[ci + 1]);
                float q2 = tanhf(acc[i][nt][2] + B1S[ci]);
                float q3 = tanhf(acc[i][nt][3] + B1S[ci + 1]);
                int a0 = ((mt * 32 + n8) * 2) * 32 + l;
                split2(q0, q1, AH[a0], AL[a0]);
                split2(q2, q3, AH[a0 + 32], AL[a0 + 32]);
            }
        }
        __syncthreads();
        // GEMM2: D = A @ W2^T
        ZACC();
        gemm_acc(AH, AL, 32, W2fh, W2fl, 16, mw, nw, l, acc);
        __syncthreads();
        // epi2: k_stg = D + b2 ; A = next stage input (or h update at stg 6)
        float cf0 = 0.f, cf1 = 0.f, cf2 = 0.f, cf3 = 0.f, cfd = 0.f;
        if (stg < 6) {
            cf0 = CF[stg - 1][0]; cf1 = CF[stg - 1][1];
            cf2 = CF[stg - 1][2]; cf3 = CF[stg - 1][3];
            cfd = CF[stg - 1][stg - 1];
        }
        float* kw = (stg == 1) ? gK1 : (stg == 2) ? gK2 : (stg == 3) ? gK3
                  : (stg == 4) ? gK4 : gK5;
#pragma unroll
        for (int i = 0; i < 2; i++) {
            int mt = 2 * mw + i;
            float dt0 = DTS[mt * 16 + (l >> 2)], dt1 = DTS[mt * 16 + 8 + (l >> 2)];
#pragma unroll
            for (int nt = 0; nt < 16; nt++) {
                int n8 = nw * 16 + nt, ci = n8 * 8 + 2 * (l & 3);
                size_t g0 = cbb + (size_t)(((mt * 32 + n8) * 4) * 32 + l);
                float kv[4], av[4];
                kv[0] = acc[i][nt][0] + B2S[ci];     kv[1] = acc[i][nt][1] + B2S[ci + 1];
                kv[2] = acc[i][nt][2] + B2S[ci];     kv[3] = acc[i][nt][3] + B2S[ci + 1];
                if (stg == 6) {
#pragma unroll
                    for (int r = 0; r < 4; r++) {
                        size_t gg = g0 + 32 * r;
                        float hn = gH[gg] + (r < 2 ? dt0 : dt1) *
                            (C1f * gK1[gg] + C3f * gK3[gg] + C4f * gK4[gg] +
                             C5f * gK5[gg] + C6f * kv[r]);
                        gH[gg] = hn;
                        av[r] = hn;
                    }
                } else {
#pragma unroll
                    for (int r = 0; r < 4; r++) {
                        size_t gg = g0 + 32 * r;
                        kw[gg] = kv[r];
                        float s = cfd * kv[r];
                        if (stg > 1) s += cf0 * gK1[gg];
                        if (stg > 2) s += cf1 * gK2[gg];
                        if (stg > 3) s += cf2 * gK3[gg];
                        if (stg > 4) s += cf3 * gK4[gg];
                        av[r] = gH[gg] + (r < 2 ? dt0 : dt1) * s;
                    }
                }
                int a0 = ((mt * 32 + n8) * 2) * 32 + l;
                split2(av[0], av[1], AH[a0], AL[a0]);
                split2(av[2], av[3], AH[a0 + 32], AL[a0 + 32]);
            }
        }
        __syncthreads();
    }

    // ================= LSTM x2 =================
    // x fragments (built once; A already holds h from stage-6 epi)
#pragma unroll 1
    for (int s = t; s < 8192; s += 256) {
        int la = s & 31, hf = (s >> 5) & 1, k8 = (s >> 6) & 15, mt = s >> 10;
        int r = mt * 16 + hf * 8 + (la >> 2), c = k8 * 8 + 2 * (la & 3);
        size_t gs = (size_t)(rb + r) * 128 + c;
        split2(x[gs], x[gs + 1], XH[s], XL[s]);
    }
    __syncthreads();

#pragma unroll 1
    for (int cell = 0; cell < 2; cell++) {
#pragma unroll 1
        for (int g = 0; g < 4; g++) {
            ZACC();
            gemm_acc(AH, AL, 32, Whhfh + g * 32768, Whhfl + g * 32768, 16, mw, nw, l, acc);
            gemm_acc(XH, XL, 16, Wihfh + g * 16384, Wihfl + g * 16384, 8, mw, nw, l, acc);
            float* kw = (g == 0) ? gK1 : (g == 1) ? gK2 : (g == 2) ? gK3 : gK4;
#pragma unroll
            for (int i = 0; i < 2; i++) {
                int mt = 2 * mw + i;
#pragma unroll
                for (int nt = 0; nt < 16; nt++) {
                    int n8 = nw * 16 + nt, ci = g * 256 + n8 * 8 + 2 * (l & 3);
                    size_t g0 = cbb + (size_t)(((mt * 32 + n8) * 4) * 32 + l);
                    float v0 = acc[i][nt][0] + BZS[ci], v1 = acc[i][nt][1] + BZS[ci + 1];
                    float v2 = acc[i][nt][2] + BZS[ci], v3 = acc[i][nt][3] + BZS[ci + 1];
                    if (g == 2) { v0 = tanhf(v0); v1 = tanhf(v1); v2 = tanhf(v2); v3 = tanhf(v3); }
                    else        { v0 = sigm(v0);  v1 = sigm(v1);  v2 = sigm(v2);  v3 = sigm(v3);  }
                    kw[g0] = v0; kw[g0 + 32] = v1; kw[g0 + 64] = v2; kw[g0 + 96] = v3;
                }
            }
        }
        __syncthreads();   // all gate GEMMs done reading A before combine rewrites A
        // combine: c = f*c + i*g ; h = o*tanh(c) ; A = h
#pragma unroll
        for (int i = 0; i < 2; i++) {
            int mt = 2 * mw + i;
#pragma unroll
            for (int nt = 0; nt < 16; nt++) {
                int n8 = nw * 16 + nt;
                size_t g0 = cbb + (size_t)(((mt * 32 + n8) * 4) * 32 + l);
                float hv[4];
#pragma unroll
                for (int r = 0; r < 4; r++) {
                    size_t gg = g0 + 32 * r;
                    float cn = gK2[gg] * gC[gg] + gK1[gg] * gK3[gg];
                    gC[gg] = cn;
                    hv[r] = gK4[gg] * tanhf(cn);
                    gH[gg] = hv[r];
                }
                int a0 = ((mt * 32 + n8) * 2) * 32 + l;
                split2(hv[0], hv[1], AH[a0], AL[a0]);
                split2(hv[2], hv[3], AH[a0 + 32], AL[a0 + 32]);
            }
        }
        __syncthreads();
    }

    // ================= output =================
    const size_t BH = (size_t)BT * 256;
#pragma unroll
    for (int i = 0; i < 2; i++) {
        int mt = 2 * mw + i;
        int r0 = rb + mt * 16 + (l >> 2);
#pragma unroll
        for (int nt = 0; nt < 16; nt++) {
            int n8 = nw * 16 + nt, c = n8 * 8 + 2 * (l & 3);
            size_t g0 = cbb + (size_t)(((mt * 32 + n8) * 4) * 32 + l);
            float2 v;
            v.x = gH[g0];      v.y = gH[g0 + 32];
            *(float2*)&out[(size_t)r0 * 256 + c] = v;
            v.x = gH[g0 + 64]; v.y = gH[g0 + 96];
            *(float2*)&out[(size_t)(r0 + 8) * 256 + c] = v;
            v.x = gC[g0];      v.y = gC[g0 + 32];
            *(float2*)&out[BH + (size_t)r0 * 256 + c] = v;
            v.x = gC[g0 + 64]; v.y = gC[g0 + 96];
            *(float2*)&out[BH + (size_t)(r0 + 8) * 256 + c] = v;
        }
    }
}

extern "C" void kernel_launch(void* const* d_in, const int* in_sizes, int n_in,
                              void* d_out, int out_size) {
    const float* x    = (const float*)d_in[0];
    const float* h0   = (const float*)d_in[1];
    const float* c0   = (const float*)d_in[2];
    const float* ts   = (const float*)d_in[3];
    const float* W_ih = (const float*)d_in[4];
    const float* W_hh = (const float*)d_in[5];
    const float* b_ih = (const float*)d_in[6];
    const float* b_hh = (const float*)d_in[7];
    const float* W1   = (const float*)d_in[8];
    const float* b1   = (const float*)d_in[9];
    const float* W2   = (const float*)d_in[10];
    const float* b2   = (const float*)d_in[11];
    float* out = (float*)d_out;

    cudaFuncSetAttribute(ode_main, cudaFuncAttributeMaxDynamicSharedMemorySize, SMEM_SZ);

    prep_w<<<256, 256>>>(W1, W2, W_ih, W_hh);
    ode_main<<<128, 256, SMEM_SZ>>>(x, h0, c0, ts, b_ih, b_hh, b1, b2, out);
}